// round 2
// baseline (speedup 1.0000x reference)
#include <cuda_runtime.h>
#include <cuda_bf16.h>
#include <mma.h>
#include <math.h>

using namespace nvcuda;

// ---------------- problem constants ----------------
#define NBOX   1000
#define FH     38
#define FW     50
#define FC     512
#define FC4    128          // FC/4 (float4 channels)
#define CROP   14
#define RS     7
#define DFLAT  25088        // 7*7*512
#define D1     4096
#define NCLS   21
#define NREG   80

// ---------------- scratch (device globals; no allocations allowed) ----------
__device__ float g_pooled[(size_t)NBOX * DFLAT];  // ~100 MB
__device__ float g_x1[(size_t)NBOX * D1];
__device__ float g_x2[(size_t)NBOX * D1];

// tf32 round-to-nearest (unbiased; raw truncation would bias the GEMM ~1e-3)
__device__ __forceinline__ float tf32r(float x) {
    asm("cvt.rna.tf32.f32 %0, %0;" : "+f"(x));
    return x;
}

// ===================== Kernel 1: crop_and_resize + 2x2 maxpool ==============
// pooled[n, py, px, c] = max_{dy,dx in 2x2} bilinear(feats, 2py+dy, 2px+dx)
__global__ __launch_bounds__(256) void roi_pool_kernel(
    const float* __restrict__ feats, const float* __restrict__ boxes)
{
    int n = blockIdx.x;
    __shared__ int   sy0[CROP], sy1[CROP], sx0[CROP], sx1[CROP];
    __shared__ float swy[CROP], swx[CROP];

    int t = threadIdx.x;
    if (t < 2 * CROP) {
        int  i   = t % CROP;
        bool isY = (t < CROP);
        float b1 = boxes[n * 4 + (isY ? 0 : 1)];
        float b2 = boxes[n * 4 + (isY ? 2 : 3)];
        float S  = isY ? (float)(FH - 1) : (float)(FW - 1);
        int   lim = isY ? (FH - 1) : (FW - 1);
        float v  = b1 * S + (float)i * ((b2 - b1) * S / (float)(CROP - 1));
        float f  = floorf(v);
        int i0 = (int)f;
        i0 = min(max(i0, 0), lim);
        int i1 = min(i0 + 1, lim);
        float w = v - f;
        if (isY) { sy0[i] = i0; sy1[i] = i1; swy[i] = w; }
        else     { sx0[i] = i0; sx1[i] = i1; swx[i] = w; }
    }
    __syncthreads();

    const float4* F4 = reinterpret_cast<const float4*>(feats);
    float4* P4 = reinterpret_cast<float4*>(g_pooled);

    // 7*7*128 float4 outputs per box
    for (int idx = t; idx < RS * RS * FC4; idx += 256) {
        int c4 = idx & (FC4 - 1);
        int p  = idx >> 7;          // 0..48
        int px = p % RS;
        int py = p / RS;

        float4 best = make_float4(-3.4e38f, -3.4e38f, -3.4e38f, -3.4e38f);
        #pragma unroll
        for (int dy = 0; dy < 2; dy++) {
            int iy = 2 * py + dy;
            int y0 = sy0[iy], y1 = sy1[iy];
            float wy = swy[iy], omwy = 1.f - wy;
            #pragma unroll
            for (int dx = 0; dx < 2; dx++) {
                int ix = 2 * px + dx;
                int x0 = sx0[ix], x1 = sx1[ix];
                float wx = swx[ix], omwx = 1.f - wx;
                float4 a = F4[(y0 * FW + x0) * FC4 + c4];
                float4 b = F4[(y0 * FW + x1) * FC4 + c4];
                float4 c = F4[(y1 * FW + x0) * FC4 + c4];
                float4 d = F4[(y1 * FW + x1) * FC4 + c4];
                float4 v;
                v.x = (a.x * omwx + b.x * wx) * omwy + (c.x * omwx + d.x * wx) * wy;
                v.y = (a.y * omwx + b.y * wx) * omwy + (c.y * omwx + d.y * wx) * wy;
                v.z = (a.z * omwx + b.z * wx) * omwy + (c.z * omwx + d.z * wx) * wy;
                v.w = (a.w * omwx + b.w * wx) * omwy + (c.w * omwx + d.w * wx) * wy;
                best.x = fmaxf(best.x, v.x);
                best.y = fmaxf(best.y, v.y);
                best.z = fmaxf(best.z, v.z);
                best.w = fmaxf(best.w, v.w);
            }
        }
        P4[(size_t)n * (RS * RS * FC4) + p * FC4 + c4] = best;
    }
}

// ===================== Kernel 2: tf32 wmma GEMM + bias + relu ===============
// C[M,N] = relu(A[M,K] @ B[K,N] + bias), tf32 inputs (RN-rounded), fp32 accum.
// CTA tile 128x128, k-tile 32, 8 warps as 2(M)x4(N), warp tile 64x32.
#define BM 128
#define BN 128
#define BK 32

__global__ __launch_bounds__(256) void gemm_bias_relu_kernel(
    int mode,                        // 0: pooled->x1  1: x1->x2
    const float* __restrict__ B, const float* __restrict__ bias,
    int M, int N, int K)
{
    const float* A = (mode == 0) ? g_pooled : g_x1;
    float*       C = (mode == 0) ? g_x1 : g_x2;

    __shared__ float As[BM][BK + 4];
    __shared__ float Bs[BK][BN + 4];
    __shared__ float stage[8][16][20];   // ldm=20: multiple of 4 floats (16B) as WMMA requires

    int tid = threadIdx.x;
    int warpId = tid >> 5;
    int lane = tid & 31;
    int m0 = blockIdx.y * BM;
    int n0 = blockIdx.x * BN;
    int wm = warpId & 1;     // 2 M-groups of 64
    int wn = warpId >> 1;    // 4 N-groups of 32

    wmma::fragment<wmma::accumulator, 16, 16, 8, float> acc[4][2];
    #pragma unroll
    for (int i = 0; i < 4; i++)
        #pragma unroll
        for (int j = 0; j < 2; j++)
            wmma::fill_fragment(acc[i][j], 0.0f);

    for (int k0 = 0; k0 < K; k0 += BK) {
        // A tile: 128 rows x 32 cols (1024 float4 loads)
        #pragma unroll
        for (int i = 0; i < 4; i++) {
            int li = tid + i * 256;
            int row = li >> 3;
            int c4 = li & 7;
            int gm = m0 + row;
            float4 v = make_float4(0.f, 0.f, 0.f, 0.f);
            if (gm < M)
                v = *reinterpret_cast<const float4*>(A + (size_t)gm * K + k0 + c4 * 4);
            As[row][c4 * 4 + 0] = tf32r(v.x);
            As[row][c4 * 4 + 1] = tf32r(v.y);
            As[row][c4 * 4 + 2] = tf32r(v.z);
            As[row][c4 * 4 + 3] = tf32r(v.w);
        }
        // B tile: 32 rows x 128 cols
        #pragma unroll
        for (int i = 0; i < 4; i++) {
            int li = tid + i * 256;
            int row = li >> 5;
            int c4 = li & 31;
            float4 v = *reinterpret_cast<const float4*>(
                B + (size_t)(k0 + row) * N + n0 + c4 * 4);
            Bs[row][c4 * 4 + 0] = tf32r(v.x);
            Bs[row][c4 * 4 + 1] = tf32r(v.y);
            Bs[row][c4 * 4 + 2] = tf32r(v.z);
            Bs[row][c4 * 4 + 3] = tf32r(v.w);
        }
        __syncthreads();

        #pragma unroll
        for (int kk = 0; kk < BK; kk += 8) {
            wmma::fragment<wmma::matrix_a, 16, 16, 8, wmma::precision::tf32, wmma::row_major> af[4];
            wmma::fragment<wmma::matrix_b, 16, 16, 8, wmma::precision::tf32, wmma::row_major> bf[2];
            #pragma unroll
            for (int i = 0; i < 4; i++)
                wmma::load_matrix_sync(af[i], &As[wm * 64 + i * 16][kk], BK + 4);
            #pragma unroll
            for (int j = 0; j < 2; j++)
                wmma::load_matrix_sync(bf[j], &Bs[kk][wn * 32 + j * 16], BN + 4);
            #pragma unroll
            for (int i = 0; i < 4; i++)
                #pragma unroll
                for (int j = 0; j < 2; j++)
                    wmma::mma_sync(acc[i][j], af[i], bf[j], acc[i][j]);
        }
        __syncthreads();
    }

    // epilogue: per-warp stage through smem for bounds + bias + relu
    #pragma unroll
    for (int i = 0; i < 4; i++) {
        #pragma unroll
        for (int j = 0; j < 2; j++) {
            wmma::store_matrix_sync(&stage[warpId][0][0], acc[i][j], 20, wmma::mem_row_major);
            __syncwarp();
            #pragma unroll
            for (int e = lane; e < 256; e += 32) {
                int r = e >> 4, cc = e & 15;
                int gm = m0 + wm * 64 + i * 16 + r;
                int gn = n0 + wn * 32 + j * 16 + cc;
                if (gm < M) {
                    float v = stage[warpId][r][cc] + bias[gn];
                    C[(size_t)gm * N + gn] = fmaxf(v, 0.0f);
                }
            }
            __syncwarp();
        }
    }
}

// ===================== Kernel 3: heads (cls softmax + reg) ==================
// One block per row. 8 warps: warps split the K range in half (2x101 partials);
// lanes map to output columns so W loads are contiguous per row.
__global__ __launch_bounds__(256) void heads_kernel(
    const float* __restrict__ Wc, const float* __restrict__ bc,
    const float* __restrict__ Wr, const float* __restrict__ br,
    float* __restrict__ out)
{
    int n = blockIdx.x;
    __shared__ float xs[D1];
    __shared__ float partial[2][104];
    __shared__ float res[104];

    int t = threadIdx.x;
    {
        const float4* X4 = reinterpret_cast<const float4*>(g_x2 + (size_t)n * D1);
        float4* S4 = reinterpret_cast<float4*>(xs);
        for (int i = t; i < D1 / 4; i += 256) S4[i] = X4[i];
    }
    __syncthreads();

    int warpId = t >> 5, lane = t & 31;
    int half = warpId >> 2;     // 0/1 : K range half
    int wgrp = warpId & 3;      // 0..3 : column group
    int c = wgrp * 32 + lane;   // 0..127 (valid < 101)
    int kb = half * (D1 / 2);

    if (c < NCLS + NREG) {
        float s = 0.f;
        if (c < NCLS) {
            #pragma unroll 4
            for (int k = kb; k < kb + D1 / 2; k++)
                s += xs[k] * Wc[(size_t)k * NCLS + c];
        } else {
            int cr = c - NCLS;
            #pragma unroll 4
            for (int k = kb; k < kb + D1 / 2; k++)
                s += xs[k] * Wr[(size_t)k * NREG + cr];
        }
        partial[half][c] = s;
    }
    __syncthreads();

    if (t < NCLS + NREG) {
        float v = partial[0][t] + partial[1][t];
        v += (t < NCLS) ? bc[t] : br[t - NCLS];
        res[t] = v;
    }
    __syncthreads();

    // reg_out: rows of 80 after the 1000x21 cls block
    if (t < NREG)
        out[(size_t)NBOX * NCLS + (size_t)n * NREG + t] = res[NCLS + t];

    // softmax over 21 by warp 0
    if (warpId == 0) {
        float v = (lane < NCLS) ? res[lane] : -3.4e38f;
        float m = v;
        #pragma unroll
        for (int o = 16; o; o >>= 1) m = fmaxf(m, __shfl_xor_sync(0xffffffff, m, o));
        float e = (lane < NCLS) ? expf(v - m) : 0.f;
        float ssum = e;
        #pragma unroll
        for (int o = 16; o; o >>= 1) ssum += __shfl_xor_sync(0xffffffff, ssum, o);
        if (lane < NCLS)
            out[(size_t)n * NCLS + lane] = e / ssum;
    }
}

// ===================== launcher ============================================
extern "C" void kernel_launch(void* const* d_in, const int* in_sizes, int n_in,
                              void* d_out, int out_size)
{
    const float* feats = (const float*)d_in[0];
    const float* boxes = (const float*)d_in[1];
    const float* W1    = (const float*)d_in[2];
    const float* b1    = (const float*)d_in[3];
    const float* W2    = (const float*)d_in[4];
    const float* b2    = (const float*)d_in[5];
    const float* Wc    = (const float*)d_in[6];
    const float* bc    = (const float*)d_in[7];
    const float* Wr    = (const float*)d_in[8];
    const float* br    = (const float*)d_in[9];
    float* out = (float*)d_out;

    roi_pool_kernel<<<NBOX, 256>>>(feats, boxes);

    dim3 grid1(D1 / BN, (NBOX + BM - 1) / BM);   // (32, 8)
    gemm_bias_relu_kernel<<<grid1, 256>>>(0, W1, b1, NBOX, D1, DFLAT);
    gemm_bias_relu_kernel<<<grid1, 256>>>(1, W2, b2, NBOX, D1, D1);

    heads_kernel<<<NBOX, 256>>>(Wc, bc, Wr, br, out);
}

// round 7
// speedup vs baseline: 4.6485x; 4.6485x over previous
#include <cuda_runtime.h>
#include <cuda_fp16.h>
#include <mma.h>
#include <math.h>
#include <stdint.h>

using namespace nvcuda;

// ---------------- problem constants ----------------
#define NBOX   1000
#define FH     38
#define FW     50
#define FC     512
#define FC4    128
#define CROP   14
#define RS     7
#define DFLAT  25088        // 7*7*512
#define D1     4096
#define NCLS   21
#define NREG   80

// ---------------- scratch (device globals; no allocations allowed) ----------
__device__ __half g_pooledh[(size_t)NBOX * DFLAT];  // 50 MB, fp16 A of GEMM1
__device__ __half g_w1h[(size_t)DFLAT * D1];        // 205 MB, fp16 W1 [K][N]
__device__ __half g_w2h[(size_t)D1 * D1];           // 33.5 MB, fp16 W2 [K][N]
__device__ __half g_x1h[(size_t)NBOX * D1];         // fp16 A of GEMM2
__device__ float  g_x2[(size_t)NBOX * D1];          // fp32, heads input

// ---------------- helpers ----------------
__device__ __forceinline__ uint32_t smem_u32(const void* p) {
    uint32_t a;
    asm("{ .reg .u64 t; cvta.to.shared.u64 t, %1; cvt.u32.u64 %0, t; }" : "=r"(a) : "l"(p));
    return a;
}
__device__ __forceinline__ void cp_async16(uint32_t dst, const void* src, int sz) {
    asm volatile("cp.async.cg.shared.global [%0], [%1], 16, %2;" :: "r"(dst), "l"(src), "r"(sz));
}
#define CP_COMMIT() asm volatile("cp.async.commit_group;" ::: "memory")
#define CP_WAIT(n)  asm volatile("cp.async.wait_group %0;" :: "n"(n) : "memory")

// ===================== Kernel 0: fp32 -> fp16 convert (RN) ==================
__global__ __launch_bounds__(256) void convert_half_kernel(
    const float* __restrict__ src, __half* __restrict__ dst, size_t n4)
{
    size_t i = (size_t)blockIdx.x * blockDim.x + threadIdx.x;
    if (i < n4) {
        float4 v = reinterpret_cast<const float4*>(src)[i];
        __half2* d = reinterpret_cast<__half2*>(dst) + 2 * i;
        d[0] = __floats2half2_rn(v.x, v.y);
        d[1] = __floats2half2_rn(v.z, v.w);
    }
}

// ===================== Kernel 1: crop_and_resize + 2x2 maxpool (fp16 out) ===
__global__ __launch_bounds__(256) void roi_pool_kernel(
    const float* __restrict__ feats, const float* __restrict__ boxes)
{
    int n = blockIdx.x;
    __shared__ int   sy0[CROP], sy1[CROP], sx0[CROP], sx1[CROP];
    __shared__ float swy[CROP], swx[CROP];

    int t = threadIdx.x;
    if (t < 2 * CROP) {
        int  i   = t % CROP;
        bool isY = (t < CROP);
        float b1 = boxes[n * 4 + (isY ? 0 : 1)];
        float b2 = boxes[n * 4 + (isY ? 2 : 3)];
        float S  = isY ? (float)(FH - 1) : (float)(FW - 1);
        int   lim = isY ? (FH - 1) : (FW - 1);
        float v  = b1 * S + (float)i * ((b2 - b1) * S / (float)(CROP - 1));
        float f  = floorf(v);
        int i0 = (int)f;
        i0 = min(max(i0, 0), lim);
        int i1 = min(i0 + 1, lim);
        float w = v - f;
        if (isY) { sy0[i] = i0; sy1[i] = i1; swy[i] = w; }
        else     { sx0[i] = i0; sx1[i] = i1; swx[i] = w; }
    }
    __syncthreads();

    const float4* F4 = reinterpret_cast<const float4*>(feats);
    __half2* H2 = reinterpret_cast<__half2*>(g_pooledh);

    for (int idx = t; idx < RS * RS * FC4; idx += 256) {
        int c4 = idx & (FC4 - 1);
        int p  = idx >> 7;
        int px = p % RS;
        int py = p / RS;

        float4 best = make_float4(-3.4e38f, -3.4e38f, -3.4e38f, -3.4e38f);
        #pragma unroll
        for (int dy = 0; dy < 2; dy++) {
            int iy = 2 * py + dy;
            int y0 = sy0[iy], y1 = sy1[iy];
            float wy = swy[iy], omwy = 1.f - wy;
            #pragma unroll
            for (int dx = 0; dx < 2; dx++) {
                int ix = 2 * px + dx;
                int x0 = sx0[ix], x1 = sx1[ix];
                float wx = swx[ix], omwx = 1.f - wx;
                float4 a = F4[(y0 * FW + x0) * FC4 + c4];
                float4 b = F4[(y0 * FW + x1) * FC4 + c4];
                float4 c = F4[(y1 * FW + x0) * FC4 + c4];
                float4 d = F4[(y1 * FW + x1) * FC4 + c4];
                float4 v;
                v.x = (a.x * omwx + b.x * wx) * omwy + (c.x * omwx + d.x * wx) * wy;
                v.y = (a.y * omwx + b.y * wx) * omwy + (c.y * omwx + d.y * wx) * wy;
                v.z = (a.z * omwx + b.z * wx) * omwy + (c.z * omwx + d.z * wx) * wy;
                v.w = (a.w * omwx + b.w * wx) * omwy + (c.w * omwx + d.w * wx) * wy;
                best.x = fmaxf(best.x, v.x);
                best.y = fmaxf(best.y, v.y);
                best.z = fmaxf(best.z, v.z);
                best.w = fmaxf(best.w, v.w);
            }
        }
        size_t base = (size_t)n * DFLAT + (size_t)p * FC + c4 * 4;
        H2[base / 2]     = __floats2half2_rn(best.x, best.y);
        H2[base / 2 + 1] = __floats2half2_rn(best.z, best.w);
    }
}

// ===================== Kernel 2: fp16 wmma GEMM + bias + relu ===============
// C[M,N] = relu(A[M,K] @ B[K,N] + bias). A,B fp16 row-major, fp32 accum.
// 128x128x32 CTA tile, 4-stage cp.async pipeline, 8 warps (2M x 4N, 64x32 each).
#define GNS 4
#define BM 128
#define BN 128
#define BK 32
#define APAD 8
#define BPAD 8
#define AS_STRIDE (BK + APAD)                 // 40 halves (80 B, 16B-mult)
#define BS_STRIDE (BN + BPAD)                 // 136 halves (272 B, 16B-mult)
#define A_TILE_BYTES (BM * AS_STRIDE * 2)     // 10240
#define B_TILE_BYTES (BK * BS_STRIDE * 2)     // 8704
#define STAGE_BYTES  (A_TILE_BYTES + B_TILE_BYTES)   // 18944
#define GEMM_DSMEM   (GNS * STAGE_BYTES)      // 75776

__global__ __launch_bounds__(256, 2) void gemm_fp16_kernel(
    const __half* __restrict__ A, const __half* __restrict__ B,
    const float* __restrict__ bias, void* __restrict__ Cv,
    int M, int N, int K, int half_out)
{
    extern __shared__ char dsm[];
    int tid = threadIdx.x, warpId = tid >> 5, lane = tid & 31;
    int m0 = blockIdx.y * BM, n0 = blockIdx.x * BN;
    int wm = warpId & 1;      // 2 M-groups of 64
    int wn = warpId >> 1;     // 4 N-groups of 32
    const int KT = K / BK;

    wmma::fragment<wmma::accumulator, 16, 16, 16, float> acc[4][2];
    #pragma unroll
    for (int i = 0; i < 4; i++)
        #pragma unroll
        for (int j = 0; j < 2; j++)
            wmma::fill_fragment(acc[i][j], 0.0f);

    auto load_tile = [&](int j) {
        char* st = dsm + (j & (GNS - 1)) * STAGE_BYTES;
        uint32_t sA = smem_u32(st);
        uint32_t sB = sA + A_TILE_BYTES;
        int kb = j * BK;
        // A tile: 128 rows x 32 halves = 512 chunks of 16B (4 chunks/row)
        #pragma unroll
        for (int i = 0; i < 2; i++) {
            int idx = i * 256 + tid;
            int row = idx >> 2, c = idx & 3;
            int gm = m0 + row;
            const __half* src = A + (size_t)min(gm, M - 1) * K + kb + c * 8;
            cp_async16(sA + row * (AS_STRIDE * 2) + c * 16, src, (gm < M) ? 16 : 0);
        }
        // B tile: 32 rows x 128 halves = 512 chunks (16 chunks/row)
        #pragma unroll
        for (int i = 0; i < 2; i++) {
            int idx = i * 256 + tid;
            int row = idx >> 4, c = idx & 15;
            const __half* src = B + (size_t)(kb + row) * N + n0 + c * 8;
            cp_async16(sB + row * (BS_STRIDE * 2) + c * 16, src, 16);
        }
        CP_COMMIT();
    };

    // prologue: stages 0..2
    for (int j = 0; j < GNS - 1; j++) load_tile(j);

    for (int it = 0; it < KT; it++) {
        CP_WAIT(GNS - 2);          // group `it` complete (exactly 1 commit/iter below)
        __syncthreads();           // all warps done with stage it-1; stage it visible

        int j = it + GNS - 1;
        if (j < KT) load_tile(j);
        else        CP_COMMIT();   // empty group keeps wait_group counting exact (tail fix)

        const char* st = dsm + (it & (GNS - 1)) * STAGE_BYTES;
        const __half* sA = reinterpret_cast<const __half*>(st);
        const __half* sB = reinterpret_cast<const __half*>(st + A_TILE_BYTES);

        #pragma unroll
        for (int kk = 0; kk < BK; kk += 16) {
            wmma::fragment<wmma::matrix_a, 16, 16, 16, __half, wmma::row_major> af[4];
            wmma::fragment<wmma::matrix_b, 16, 16, 16, __half, wmma::row_major> bf[2];
            #pragma unroll
            for (int i = 0; i < 4; i++)
                wmma::load_matrix_sync(af[i], sA + (wm * 64 + i * 16) * AS_STRIDE + kk, AS_STRIDE);
            #pragma unroll
            for (int j2 = 0; j2 < 2; j2++)
                wmma::load_matrix_sync(bf[j2], sB + kk * BS_STRIDE + wn * 32 + j2 * 16, BS_STRIDE);
            #pragma unroll
            for (int i = 0; i < 4; i++)
                #pragma unroll
                for (int j2 = 0; j2 < 2; j2++)
                    wmma::mma_sync(acc[i][j2], af[i], bf[j2], acc[i][j2]);
        }
    }

    // epilogue: stage per-warp through (reused) dynamic smem, ldm=20 (16B-mult)
    __syncthreads();
    float* stg = reinterpret_cast<float*>(dsm) + warpId * 16 * 20;
    #pragma unroll
    for (int i = 0; i < 4; i++) {
        #pragma unroll
        for (int j2 = 0; j2 < 2; j2++) {
            wmma::store_matrix_sync(stg, acc[i][j2], 20, wmma::mem_row_major);
            __syncwarp();
            #pragma unroll
            for (int e = lane; e < 256; e += 32) {
                int r = e >> 4, cc = e & 15;
                int gm = m0 + wm * 64 + i * 16 + r;
                int gn = n0 + wn * 32 + j2 * 16 + cc;
                if (gm < M) {
                    float v = fmaxf(stg[r * 20 + cc] + bias[gn], 0.0f);
                    if (half_out)
                        reinterpret_cast<__half*>(Cv)[(size_t)gm * N + gn] = __float2half_rn(v);
                    else
                        reinterpret_cast<float*>(Cv)[(size_t)gm * N + gn] = v;
                }
            }
            __syncwarp();
        }
    }
}

// ===================== Kernel 3: heads, 8 boxes per block ===================
#define HB  8
#define HCH 512
__global__ __launch_bounds__(256) void heads_kernel(
    const float* __restrict__ Wc, const float* __restrict__ bc,
    const float* __restrict__ Wr, const float* __restrict__ br,
    float* __restrict__ out)
{
    int n0 = blockIdx.x * HB;
    __shared__ float xs[HB][HCH];
    __shared__ float part[2][HB][104];
    __shared__ float res[HB][104];

    int t = threadIdx.x, wid = t >> 5, lane = t & 31;
    int h = wid >> 2, grp = wid & 3;
    int c = grp * 32 + lane;                 // output column (valid < 101)
    float acc[HB];
    #pragma unroll
    for (int b = 0; b < HB; b++) acc[b] = 0.f;

    for (int ci = 0; ci < D1 / HCH; ci++) {
        __syncthreads();
        int k0 = ci * HCH;
        #pragma unroll
        for (int i = 0; i < 4; i++) {        // 1024 float4 loads
            int idx = i * 256 + t;
            int b = idx >> 7;
            int o = idx & 127;
            reinterpret_cast<float4*>(&xs[b][0])[o] =
                reinterpret_cast<const float4*>(g_x2 + (size_t)(n0 + b) * D1 + k0)[o];
        }
        __syncthreads();
        if (c < NCLS + NREG) {
            int kk0 = h * (HCH / 2);
            if (c < NCLS) {
                const float* wp = Wc + (size_t)(k0 + kk0) * NCLS + c;
                #pragma unroll 4
                for (int k = 0; k < HCH / 2; k++) {
                    float w = wp[(size_t)k * NCLS];
                    #pragma unroll
                    for (int b = 0; b < HB; b++) acc[b] += xs[b][kk0 + k] * w;
                }
            } else {
                const float* wp = Wr + (size_t)(k0 + kk0) * NREG + (c - NCLS);
                #pragma unroll 4
                for (int k = 0; k < HCH / 2; k++) {
                    float w = wp[(size_t)k * NREG];
                    #pragma unroll
                    for (int b = 0; b < HB; b++) acc[b] += xs[b][kk0 + k] * w;
                }
            }
        }
    }
    if (c < NCLS + NREG) {
        #pragma unroll
        for (int b = 0; b < HB; b++) part[h][b][c] = acc[b];
    }
    __syncthreads();

    if (wid < HB) {
        int b = wid;
        #pragma unroll
        for (int j = 0; j < 4; j++) {
            int cc = lane + j * 32;
            if (cc < NCLS + NREG) {
                float v = part[0][b][cc] + part[1][b][cc]
                        + (cc < NCLS ? bc[cc] : br[cc - NCLS]);
                res[b][cc] = v;
                if (cc >= NCLS)
                    out[(size_t)NBOX * NCLS + (size_t)(n0 + b) * NREG + (cc - NCLS)] = v;
            }
        }
        __syncwarp();
        float v = (lane < NCLS) ? res[b][lane] : -3.4e38f;
        float m = v;
        #pragma unroll
        for (int o = 16; o; o >>= 1) m = fmaxf(m, __shfl_xor_sync(0xffffffff, m, o));
        float e = (lane < NCLS) ? expf(v - m) : 0.f;
        float ssum = e;
        #pragma unroll
        for (int o = 16; o; o >>= 1) ssum += __shfl_xor_sync(0xffffffff, ssum, o);
        if (lane < NCLS)
            out[(size_t)(n0 + b) * NCLS + lane] = e / ssum;
    }
}

// ===================== launcher ============================================
extern "C" void kernel_launch(void* const* d_in, const int* in_sizes, int n_in,
                              void* d_out, int out_size)
{
    const float* feats = (const float*)d_in[0];
    const float* boxes = (const float*)d_in[1];
    const float* W1    = (const float*)d_in[2];
    const float* b1    = (const float*)d_in[3];
    const float* W2    = (const float*)d_in[4];
    const float* b2    = (const float*)d_in[5];
    const float* Wc    = (const float*)d_in[6];
    const float* bc    = (const float*)d_in[7];
    const float* Wr    = (const float*)d_in[8];
    const float* br    = (const float*)d_in[9];
    float* out = (float*)d_out;

    __half* w1h;  cudaGetSymbolAddress((void**)&w1h, g_w1h);
    __half* w2h;  cudaGetSymbolAddress((void**)&w2h, g_w2h);
    __half* ph;   cudaGetSymbolAddress((void**)&ph,  g_pooledh);
    __half* x1h;  cudaGetSymbolAddress((void**)&x1h, g_x1h);
    float*  x2;   cudaGetSymbolAddress((void**)&x2,  g_x2);

    cudaFuncSetAttribute(gemm_fp16_kernel,
                         cudaFuncAttributeMaxDynamicSharedMemorySize, GEMM_DSMEM);

    // weight converts (fp32 -> fp16, RN)
    {
        size_t n4 = ((size_t)DFLAT * D1) / 4;
        convert_half_kernel<<<(unsigned)((n4 + 255) / 256), 256>>>(W1, w1h, n4);
    }
    {
        size_t n4 = ((size_t)D1 * D1) / 4;
        convert_half_kernel<<<(unsigned)((n4 + 255) / 256), 256>>>(W2, w2h, n4);
    }

    roi_pool_kernel<<<NBOX, 256>>>(feats, boxes);

    dim3 g1(D1 / BN, (NBOX + BM - 1) / BM);   // (32, 8)
    gemm_fp16_kernel<<<g1, 256, GEMM_DSMEM>>>(ph,  w1h, b1, x1h, NBOX, D1, DFLAT, 1);
    gemm_fp16_kernel<<<g1, 256, GEMM_DSMEM>>>(x1h, w2h, b2, x2,  NBOX, D1, D1,    0);

    heads_kernel<<<NBOX / HB, 256>>>(Wc, bc, Wr, br, out);
}